// round 9
// baseline (speedup 1.0000x reference)
#include <cuda_runtime.h>
#include <math.h>

#define NB 8
#define NC 19
#define HW (512 * 512)
#define HW2 (HW / 2)
#define SMOOTH 1e-08f
#define GRID_X 37
#define NBLOCKS (GRID_X * NB)
#define NTHREADS 256
#define CHUNK ((HW2 + GRID_X - 1) / GRID_X)   // 3543 float2 per CTA, contiguous

__device__ float g_acc[2 * NB * NC];   // [0..152)=tp, [152..304)=den
__device__ unsigned int g_done = 0;

__global__ __launch_bounds__(NTHREADS, 2) void tversky_fused_kernel(
    const float* __restrict__ pred, const int* __restrict__ target,
    float* __restrict__ out) {
    const int b = blockIdx.y;
    const float2* __restrict__ p2 =
        (const float2*)(pred + (size_t)b * NC * HW);
    const int2* __restrict__ t2 = (const int2*)(target + (size_t)b * HW);
    const int tid = threadIdx.x;

    __shared__ float s_acc[2 * NC];   // tp, den
    __shared__ int s_is_last;
    if (tid < 2 * NC) s_acc[tid] = 0.0f;
    __syncthreads();

    float rtp[NC], rden[NC];
#pragma unroll
    for (int c = 0; c < NC; c++) { rtp[c] = 0.0f; rden[c] = 0.0f; }

    // contiguous tile: this CTA owns [lo, hi) of HW2 — every class stream
    // advances sequentially 2KB/iter for DRAM row-buffer locality
    const int lo = blockIdx.x * CHUNK;
    const int hi = min(lo + CHUNK, HW2);
    for (int idx = lo + tid; idx < hi; idx += NTHREADS) {
        float2 e[NC];
#pragma unroll
        for (int c = 0; c < NC; c++) e[c] = p2[(size_t)c * HW2 + idx];
        const int2 tg = t2[idx];

        float sx = 0.0f, sy = 0.0f;
#pragma unroll
        for (int c = 0; c < NC; c++) {
            e[c].x = __expf(e[c].x);
            e[c].y = __expf(e[c].y);
            sx += e[c].x;
            sy += e[c].y;
        }
        const float rx = __fdividef(1.0f, sx);
        const float ry = __fdividef(1.0f, sy);

#pragma unroll
        for (int c = 0; c < NC; c++) {
            const float px = e[c].x * rx;
            const float py = e[c].y * ry;
            rden[c] += px + py;
            if (tg.x == c) { rtp[c] += px; rden[c] += 1.0f; }
            if (tg.y == c) { rtp[c] += py; rden[c] += 1.0f; }
        }
    }

    // warp-level reduction of the 38 accumulators
#pragma unroll
    for (int c = 0; c < NC; c++) {
#pragma unroll
        for (int off = 16; off > 0; off >>= 1) {
            rtp[c]  += __shfl_down_sync(0xFFFFFFFFu, rtp[c],  off);
            rden[c] += __shfl_down_sync(0xFFFFFFFFu, rden[c], off);
        }
    }
    if ((tid & 31) == 0) {
#pragma unroll
        for (int c = 0; c < NC; c++) {
            atomicAdd(&s_acc[c], rtp[c]);
            atomicAdd(&s_acc[NC + c], rden[c]);
        }
    }
    __syncthreads();

    // block -> global (38 atomics from first 38 threads)
    if (tid < 2 * NC) {
        const int sec = tid / NC;
        const int c = tid - sec * NC;
        atomicAdd(&g_acc[sec * NB * NC + b * NC + c], s_acc[tid]);
    }

    // last-block-done epilogue
    __threadfence();
    if (tid == 0) {
        unsigned int n = atomicAdd(&g_done, 1u);
        s_is_last = (n == NBLOCKS - 1);
    }
    __syncthreads();
    if (!s_is_last) return;

    __shared__ float s_red[NTHREADS];
    float v = 0.0f;
    if (tid < NB * NC) {
        const float tp = __ldcg(&g_acc[tid]);
        const float dn = __ldcg(&g_acc[NB * NC + tid]);
        v = 1.0f - (tp + SMOOTH) / (0.5f * dn + SMOOTH);  // alpha=beta=0.5
    }
    s_red[tid] = v;
    __syncthreads();
#pragma unroll
    for (int off = NTHREADS / 2; off > 0; off >>= 1) {
        if (tid < off) s_red[tid] += s_red[tid + off];
        __syncthreads();
    }
    if (tid == 0) {
        out[0] = s_red[0] / (float)(NB * NC);
        g_done = 0u;
    }
    for (int i = tid; i < 2 * NB * NC; i += NTHREADS) g_acc[i] = 0.0f;
}

extern "C" void kernel_launch(void* const* d_in, const int* in_sizes, int n_in,
                              void* d_out, int out_size) {
    const float* pred = (const float*)d_in[0];
    const int* target = (const int*)d_in[1];
    float* out = (float*)d_out;

    dim3 grid(GRID_X, NB);
    tversky_fused_kernel<<<grid, NTHREADS>>>(pred, target, out);
}